// round 13
// baseline (speedup 1.0000x reference)
#include <cuda_runtime.h>
#include <cuda_bf16.h>
#include <cstdint>

#define SEQ    2048
#define BATCH  512
#define INPT   64
#define HIDDEN 128
#define KTOT   192
#define BB     4
#define NBLK   (BATCH / BB)    // 128 blocks, 1/SM
#define NTHR   256             // 8 warps, warp w owns j rows [16w, 16w+16)
#define NKT    (KTOT / 16)     // 12 k-tiles

__device__ __forceinline__ float tanh_fast(float z) {
    float az = fabsf(z);
    float e  = __expf(-2.0f * az);
    float r  = __fdividef(1.0f - e, 1.0f + e);
    return copysignf(r, z);
}
__device__ __forceinline__ void cp16(void* smem_dst, const float* gsrc) {
    unsigned dst = (unsigned)__cvta_generic_to_shared(smem_dst);
    asm volatile("cp.async.ca.shared.global [%0], [%1], 16;" :: "r"(dst), "l"(gsrc));
}
__device__ __forceinline__ float wcomb(const float* W_ih, const float* W_hh,
                                       int j, int c) {
    return (c < INPT) ? W_ih[j * INPT + c] : W_hh[j * HIDDEN + (c - INPT)];
}
__device__ __forceinline__ void split_bf(float v, __nv_bfloat16& hi,
                                         __nv_bfloat16& lo) {
    hi = __float2bfloat16(v);
    lo = __float2bfloat16(v - __bfloat162float(hi));
}
__device__ __forceinline__ uint32_t pack2bf(__nv_bfloat16 a, __nv_bfloat16 b) {
    __nv_bfloat162 t(a, b);                 // a -> low 16 bits
    return *reinterpret_cast<uint32_t*>(&t);
}
__device__ __forceinline__ void mma16816(float* d, const uint32_t* a,
                                         uint32_t b0, uint32_t b1) {
    asm volatile(
        "mma.sync.aligned.m16n8k16.row.col.f32.bf16.bf16.f32 "
        "{%0,%1,%2,%3}, {%4,%5,%6,%7}, {%8,%9}, {%0,%1,%2,%3};"
        : "+f"(d[0]), "+f"(d[1]), "+f"(d[2]), "+f"(d[3])
        : "r"(a[0]), "r"(a[1]), "r"(a[2]), "r"(a[3]), "r"(b0), "r"(b1));
}

// u layout (interleaved): for k-pair kp in [0,96) and batch n in [0,8):
//   uu[buf][(kp*8+n)*2 + 0] = hi word (bf16 pair k=2kp, 2kp+1)
//   uu[buf][(kp*8+n)*2 + 1] = lo word
#define IW(kp, n) (((kp) * 8 + (n)) * 2)

__global__ void __launch_bounds__(NTHR, 1)
rnn_hmma_kernel(const float* __restrict__ xs,
                const float* __restrict__ W_ih,
                const float* __restrict__ W_hh,
                const float* __restrict__ b_ih,
                const float* __restrict__ b_hh,
                const float* __restrict__ W_out,
                const float* __restrict__ b_out,
                float* __restrict__ out) {
    __shared__ __align__(16) uint32_t uu[2][96 * 8 * 2];   // 12 KB
    __shared__ __align__(16) float stage[3][BB][INPT];
    __shared__ float red[BB][HIDDEN];

    const int tid  = threadIdx.x;
    const int wid  = tid >> 5;
    const int lane = tid & 31;
    const int g    = lane >> 2;           // fragment row
    const int q    = lane & 3;            // fragment col pair
    const long bbase = (long)blockIdx.x * BB;

    const int jr0 = 16 * wid + g;         // D rows this lane owns
    const int jr1 = jr0 + 8;
    const bool act = (q < 2);
    const bool ge  = ((g & 1) == 0);
    // after the xor-4 exchange this lane finalizes j-pair (jA, jA+1)
    const int jA   = ge ? jr0 : (16 * wid + 7 + g);   // always even
    const int kpA  = 32 + (jA >> 1);

    // ---- A fragments (weights) in registers ----
    uint32_t aH[NKT][4], aL[NKT][4];
    #pragma unroll
    for (int kt = 0; kt < NKT; kt++) {
        int c0 = kt * 16 + 2 * q;
        float w00 = wcomb(W_ih, W_hh, jr0, c0);
        float w01 = wcomb(W_ih, W_hh, jr0, c0 + 1);
        float w10 = wcomb(W_ih, W_hh, jr1, c0);
        float w11 = wcomb(W_ih, W_hh, jr1, c0 + 1);
        float w02 = wcomb(W_ih, W_hh, jr0, c0 + 8);
        float w03 = wcomb(W_ih, W_hh, jr0, c0 + 9);
        float w12 = wcomb(W_ih, W_hh, jr1, c0 + 8);
        float w13 = wcomb(W_ih, W_hh, jr1, c0 + 9);
        __nv_bfloat16 h, l, h2, l2;
        split_bf(w00, h, l); split_bf(w01, h2, l2);
        aH[kt][0] = pack2bf(h, h2); aL[kt][0] = pack2bf(l, l2);
        split_bf(w10, h, l); split_bf(w11, h2, l2);
        aH[kt][1] = pack2bf(h, h2); aL[kt][1] = pack2bf(l, l2);
        split_bf(w02, h, l); split_bf(w03, h2, l2);
        aH[kt][2] = pack2bf(h, h2); aL[kt][2] = pack2bf(l, l2);
        split_bf(w12, h, l); split_bf(w13, h2, l2);
        aH[kt][3] = pack2bf(h, h2); aL[kt][3] = pack2bf(l, l2);
    }
    const float bA = b_ih[jr0] + b_hh[jr0];
    const float bB = b_ih[jr1] + b_hh[jr1];

    // ---- init: zero u, write x(0), stage x(1), x(2) ----
    for (int i = tid; i < 2 * 96 * 8 * 2; i += NTHR)
        (&uu[0][0])[i] = 0u;
    __syncthreads();
    if (tid < 128) {
        int b = tid & 3, kp = tid >> 2;
        const float* xp = xs + (bbase + b) * INPT + 2 * kp;
        __nv_bfloat16 h0, l0, h1, l1;
        split_bf(xp[0], h0, l0); split_bf(xp[1], h1, l1);
        uint2 w = { pack2bf(h0, h1), pack2bf(l0, l1) };
        *reinterpret_cast<uint2*>(&uu[0][IW(kp, b)]) = w;
    }
    if (tid < 64) {
        int b = tid >> 4, seg = tid & 15;
        cp16(&stage[1][b][seg * 4],
             xs + ((long)1 * BATCH + bbase + b) * INPT + seg * 4);
    }
    asm volatile("cp.async.commit_group;" ::);
    if (tid < 64) {
        int b = tid >> 4, seg = tid & 15;
        cp16(&stage[2][b][seg * 4],
             xs + ((long)2 * BATCH + bbase + b) * INPT + seg * 4);
    }
    asm volatile("cp.async.commit_group;" ::);
    __syncthreads();

    for (int t = 0; t < SEQ - 1; ++t) {
        const int cur = t & 1, nxt = cur ^ 1;

        // prefetch x(t+3) -> stage[t%3]
        if (t + 3 < SEQ && tid < 64) {
            int b = tid >> 4, seg = tid & 15;
            cp16(&stage[t % 3][b][seg * 4],
                 xs + ((long)(t + 3) * BATCH + bbase + b) * INPT + seg * 4);
        }
        asm volatile("cp.async.commit_group;" ::);

        // ---- 36 HMMA, 6 independent accumulator chains ----
        float D[6][4];
        #pragma unroll
        for (int c = 0; c < 6; c++)
            D[c][0] = D[c][1] = D[c][2] = D[c][3] = 0.0f;
        #pragma unroll
        for (int kt = 0; kt < NKT; kt++) {
            uint2 v0 = *reinterpret_cast<const uint2*>(
                &uu[cur][IW(kt * 8 + q, g)]);
            uint2 v1 = *reinterpret_cast<const uint2*>(
                &uu[cur][IW(kt * 8 + q + 4, g)]);
            const int c = (kt & 1) * 3;
            mma16816(D[c + 0], aH[kt], v0.x, v1.x);
            mma16816(D[c + 1], aL[kt], v0.x, v1.x);
            mma16816(D[c + 2], aH[kt], v0.y, v1.y);
        }

        // wait x(t+1) stage, convert into u[nxt] x-region
        asm volatile("cp.async.wait_group 2;" ::);
        if (tid < 128) {
            int b = tid & 3, kp = tid >> 2;
            const float* sp = &stage[(t + 1) % 3][b][2 * kp];
            __nv_bfloat16 h0, l0, h1, l1;
            split_bf(sp[0], h0, l0); split_bf(sp[1], h1, l1);
            uint2 w = { pack2bf(h0, h1), pack2bf(l0, l1) };
            *reinterpret_cast<uint2*>(&uu[nxt][IW(kp, b)]) = w;
        }

        // ---- epilogue: sums -> tanh -> pair-exchange -> one STS.128 ----
        float S0 = (D[0][0] + D[3][0]) + (D[1][0] + D[4][0]) + (D[2][0] + D[5][0]);
        float S1 = (D[0][1] + D[3][1]) + (D[1][1] + D[4][1]) + (D[2][1] + D[5][1]);
        float S2 = (D[0][2] + D[3][2]) + (D[1][2] + D[4][2]) + (D[2][2] + D[5][2]);
        float S3 = (D[0][3] + D[3][3]) + (D[1][3] + D[4][3]) + (D[2][3] + D[5][3]);
        float h0 = tanh_fast(S0 + bA);     // (jr0, col 2q)
        float h1 = tanh_fast(S1 + bA);     // (jr0, col 2q+1)
        float h2 = tanh_fast(S2 + bB);     // (jr1, col 2q)
        float h3 = tanh_fast(S3 + bB);     // (jr1, col 2q+1)
        // exchange with g^1 partner (lane xor 4)
        float e0 = __shfl_xor_sync(0xffffffffu, ge ? h2 : h0, 4);
        float e1 = __shfl_xor_sync(0xffffffffu, ge ? h3 : h1, 4);
        if (act) {
            float fA0 = ge ? h0 : e0;   // j = jA,   col 2q
            float fB0 = ge ? e0 : h2;   // j = jA+1, col 2q
            float fA1 = ge ? h1 : e1;   // j = jA,   col 2q+1
            float fB1 = ge ? e1 : h3;   // j = jA+1, col 2q+1
            __nv_bfloat16 ha, la, hb, lb;
            uint4 w;
            split_bf(fA0, ha, la); split_bf(fB0, hb, lb);
            w.x = pack2bf(ha, hb);  w.y = pack2bf(la, lb);
            split_bf(fA1, ha, la); split_bf(fB1, hb, lb);
            w.z = pack2bf(ha, hb);  w.w = pack2bf(la, lb);
            *reinterpret_cast<uint4*>(&uu[nxt][IW(kpA, 2 * q)]) = w;
        }
        __syncthreads();
    }

    // ---- peeled final step: h_final -> red (fp32) ----
    {
        const int cur = (SEQ - 1) & 1;
        float D[6][4];
        #pragma unroll
        for (int c = 0; c < 6; c++)
            D[c][0] = D[c][1] = D[c][2] = D[c][3] = 0.0f;
        #pragma unroll
        for (int kt = 0; kt < NKT; kt++) {
            uint2 v0 = *reinterpret_cast<const uint2*>(
                &uu[cur][IW(kt * 8 + q, g)]);
            uint2 v1 = *reinterpret_cast<const uint2*>(
                &uu[cur][IW(kt * 8 + q + 4, g)]);
            const int c = (kt & 1) * 3;
            mma16816(D[c + 0], aH[kt], v0.x, v1.x);
            mma16816(D[c + 1], aL[kt], v0.x, v1.x);
            mma16816(D[c + 2], aH[kt], v0.y, v1.y);
        }
        if (act) {
            float S0 = (D[0][0] + D[3][0]) + (D[1][0] + D[4][0]) + (D[2][0] + D[5][0]);
            float S1 = (D[0][1] + D[3][1]) + (D[1][1] + D[4][1]) + (D[2][1] + D[5][1]);
            float S2 = (D[0][2] + D[3][2]) + (D[1][2] + D[4][2]) + (D[2][2] + D[5][2]);
            float S3 = (D[0][3] + D[3][3]) + (D[1][3] + D[4][3]) + (D[2][3] + D[5][3]);
            red[2 * q][jr0]     = tanh_fast(S0 + bA);
            red[2 * q + 1][jr0] = tanh_fast(S1 + bA);
            red[2 * q][jr1]     = tanh_fast(S2 + bB);
            red[2 * q + 1][jr1] = tanh_fast(S3 + bB);
        }
        __syncthreads();
    }

    // ---- output projection ----
    if (wid < BB) {
        int b = wid;
        float s = 0.0f;
        #pragma unroll
        for (int m = 0; m < 4; m++) {
            int jj = lane + 32 * m;
            s += red[b][jj] * W_out[jj];
        }
        #pragma unroll
        for (int off = 16; off; off >>= 1)
            s += __shfl_down_sync(0xffffffffu, s, off);
        if (lane == 0) out[bbase + b] = s + b_out[0];
    }
}

extern "C" void kernel_launch(void* const* d_in, const int* in_sizes, int n_in,
                              void* d_out, int out_size) {
    const float* xs    = (const float*)d_in[0];
    const float* W_ih  = (const float*)d_in[1];
    const float* W_hh  = (const float*)d_in[2];
    const float* b_ih  = (const float*)d_in[3];
    const float* b_hh  = (const float*)d_in[4];
    const float* W_out = (const float*)d_in[5];
    const float* b_out = (const float*)d_in[6];

    rnn_hmma_kernel<<<NBLK, NTHR>>>(xs, W_ih, W_hh, b_ih, b_hh, W_out, b_out,
                                    (float*)d_out);
}

// round 14
// speedup vs baseline: 1.2847x; 1.2847x over previous
#include <cuda_runtime.h>
#include <cuda_bf16.h>
#include <cstdint>

#define SEQ    2048
#define BATCH  512
#define INPT   64
#define HIDDEN 128
#define BB     4
#define NBLK   (BATCH / BB)    // 128 blocks, 1/SM
#define NTHR   256             // 8 warps
#define NKT    8               // serial k-tiles (K = HIDDEN = 128)

// 512MB scratch: xp[t][b][j] = x(t,b)@W_ih^T[j] + b_ih[j] + b_hh[j]
__device__ float g_xp[(size_t)SEQ * BATCH * HIDDEN];

__device__ __forceinline__ float tanh_fast(float z) {
    float az = fabsf(z);
    float e  = __expf(-2.0f * az);
    float r  = __fdividef(1.0f - e, 1.0f + e);
    return copysignf(r, z);
}
__device__ __forceinline__ void cp16(void* smem_dst, const float* gsrc) {
    unsigned dst = (unsigned)__cvta_generic_to_shared(smem_dst);
    asm volatile("cp.async.ca.shared.global [%0], [%1], 16;" :: "r"(dst), "l"(gsrc));
}
__device__ __forceinline__ void split_bf(float v, __nv_bfloat16& hi,
                                         __nv_bfloat16& lo) {
    hi = __float2bfloat16(v);
    lo = __float2bfloat16(v - __bfloat162float(hi));
}
__device__ __forceinline__ uint32_t pack2bf(__nv_bfloat16 a, __nv_bfloat16 b) {
    __nv_bfloat162 t(a, b);                 // a -> low 16 bits
    return *reinterpret_cast<uint32_t*>(&t);
}
__device__ __forceinline__ void mma16816(float* d, const uint32_t* a,
                                         uint32_t b0, uint32_t b1) {
    asm volatile(
        "mma.sync.aligned.m16n8k16.row.col.f32.bf16.bf16.f32 "
        "{%0,%1,%2,%3}, {%4,%5,%6,%7}, {%8,%9}, {%0,%1,%2,%3};"
        : "+f"(d[0]), "+f"(d[1]), "+f"(d[2]), "+f"(d[3])
        : "r"(a[0]), "r"(a[1]), "r"(a[2]), "r"(a[3]), "r"(b0), "r"(b1));
}

// ============================================================================
// Kernel 1: xp GEMM. Block = 128 rows x 128 j. Warp w = m-tile w (16 rows).
// W_ih staged in smem, bank-exact word index widx(j, kp):
//   addr%32 = (kp&3) + 4*(j%8) -> lanes (g = j%8 gen, q = kp%4) all-distinct.
// ============================================================================
#define XROWS 128
#define XBLK  ((SEQ * BATCH) / XROWS)   // 8192

__device__ __forceinline__ int widx(int j, int kp) {
    return (kp & 3) + 4 * j + 512 * (kp >> 2);
}

__global__ void __launch_bounds__(256, 1)
xproj_hmma(const float* __restrict__ xs,
           const float* __restrict__ W_ih,
           const float* __restrict__ b_ih,
           const float* __restrict__ b_hh) {
    __shared__ uint32_t wH[4096], wL[4096];   // 32 KB
    __shared__ float biasS[HIDDEN];

    const int tid  = threadIdx.x;
    const int wid  = tid >> 5;               // m-tile
    const int lane = tid & 31;
    const int g    = lane >> 2;
    const int q    = lane & 3;
    const size_t row0 = (size_t)blockIdx.x * XROWS;

    // stage weights split hi/lo
    for (int i = tid; i < HIDDEN * 32; i += 256) {
        int kp = i & 31, j = i >> 5;
        float2 wv = *reinterpret_cast<const float2*>(W_ih + j * INPT + 2 * kp);
        __nv_bfloat16 h0, l0, h1, l1;
        split_bf(wv.x, h0, l0); split_bf(wv.y, h1, l1);
        wH[widx(j, kp)] = pack2bf(h0, h1);
        wL[widx(j, kp)] = pack2bf(l0, l1);
    }
    if (tid < HIDDEN) biasS[tid] = b_ih[tid] + b_hh[tid];
    __syncthreads();

    const size_t r0 = row0 + wid * 16 + g;
    const size_t r1 = r0 + 8;

    float acc[16][4];
    #pragma unroll
    for (int nt = 0; nt < 16; nt++)
        acc[nt][0] = acc[nt][1] = acc[nt][2] = acc[nt][3] = 0.0f;

    #pragma unroll
    for (int kt = 0; kt < 4; kt++) {
        int kp0 = kt * 8 + q;
        // A fragments from x (L1-cached across warps/kt)
        float2 x00 = *reinterpret_cast<const float2*>(xs + r0 * INPT + 2 * kp0);
        float2 x10 = *reinterpret_cast<const float2*>(xs + r1 * INPT + 2 * kp0);
        float2 x01 = *reinterpret_cast<const float2*>(xs + r0 * INPT + 2 * (kp0 + 4));
        float2 x11 = *reinterpret_cast<const float2*>(xs + r1 * INPT + 2 * (kp0 + 4));
        uint32_t aH[4], aL[4];
        __nv_bfloat16 h0, l0, h1, l1;
        split_bf(x00.x, h0, l0); split_bf(x00.y, h1, l1);
        aH[0] = pack2bf(h0, h1); aL[0] = pack2bf(l0, l1);
        split_bf(x10.x, h0, l0); split_bf(x10.y, h1, l1);
        aH[1] = pack2bf(h0, h1); aL[1] = pack2bf(l0, l1);
        split_bf(x01.x, h0, l0); split_bf(x01.y, h1, l1);
        aH[2] = pack2bf(h0, h1); aL[2] = pack2bf(l0, l1);
        split_bf(x11.x, h0, l0); split_bf(x11.y, h1, l1);
        aH[3] = pack2bf(h0, h1); aL[3] = pack2bf(l0, l1);

        #pragma unroll
        for (int nt = 0; nt < 16; nt++) {
            int j = nt * 8 + g;
            uint32_t b0h = wH[widx(j, kp0)],     b1h = wH[widx(j, kp0 + 4)];
            uint32_t b0l = wL[widx(j, kp0)],     b1l = wL[widx(j, kp0 + 4)];
            mma16816(acc[nt], aH, b0h, b1h);
            mma16816(acc[nt], aL, b0h, b1h);
            mma16816(acc[nt], aH, b0l, b1l);
        }
    }

    #pragma unroll
    for (int nt = 0; nt < 16; nt++) {
        int j0 = nt * 8 + 2 * q;
        float2 o;
        o.x = acc[nt][0] + biasS[j0];
        o.y = acc[nt][1] + biasS[j0 + 1];
        *reinterpret_cast<float2*>(g_xp + r0 * HIDDEN + j0) = o;
        o.x = acc[nt][2] + biasS[j0];
        o.y = acc[nt][3] + biasS[j0 + 1];
        *reinterpret_cast<float2*>(g_xp + r1 * HIDDEN + j0) = o;
    }
}

// ============================================================================
// Kernel 2: serial recurrence over K=128 (R12 structure, x hoisted).
// u holds only h(t): word (kp, n) at uHi/uLo[kp*8 + n], kp in [0,64).
// xp(t) staged via 4-slot cp.async ring.
// ============================================================================
__global__ void __launch_bounds__(NTHR, 1)
rnn_hmma_kernel(const float* __restrict__ W_hh,
                const float* __restrict__ W_out,
                const float* __restrict__ b_out,
                float* __restrict__ out) {
    __shared__ uint32_t uHi[2][64 * 8];
    __shared__ uint32_t uLo[2][64 * 8];
    __shared__ __align__(16) float stage[4][BB][HIDDEN];   // 8 KB
    __shared__ float red[BB][HIDDEN];

    const int tid  = threadIdx.x;
    const int wid  = tid >> 5;
    const int lane = tid & 31;
    const int g    = lane >> 2;
    const int q    = lane & 3;
    const long bbase = (long)blockIdx.x * BB;

    const int jr0 = 16 * wid + g;
    const int jr1 = jr0 + 8;
    const bool act = (q < 2);
    const int b0n = 2 * q;

    // A fragments (W_hh) in registers: 8 kt x {hi,lo} x 4 regs = 64 regs
    uint32_t aH[NKT][4], aL[NKT][4];
    #pragma unroll
    for (int kt = 0; kt < NKT; kt++) {
        int c0 = kt * 16 + 2 * q;
        float w00 = W_hh[jr0 * HIDDEN + c0];
        float w01 = W_hh[jr0 * HIDDEN + c0 + 1];
        float w10 = W_hh[jr1 * HIDDEN + c0];
        float w11 = W_hh[jr1 * HIDDEN + c0 + 1];
        float w02 = W_hh[jr0 * HIDDEN + c0 + 8];
        float w03 = W_hh[jr0 * HIDDEN + c0 + 9];
        float w12 = W_hh[jr1 * HIDDEN + c0 + 8];
        float w13 = W_hh[jr1 * HIDDEN + c0 + 9];
        __nv_bfloat16 h, l, h2, l2;
        split_bf(w00, h, l); split_bf(w01, h2, l2);
        aH[kt][0] = pack2bf(h, h2); aL[kt][0] = pack2bf(l, l2);
        split_bf(w10, h, l); split_bf(w11, h2, l2);
        aH[kt][1] = pack2bf(h, h2); aL[kt][1] = pack2bf(l, l2);
        split_bf(w02, h, l); split_bf(w03, h2, l2);
        aH[kt][2] = pack2bf(h, h2); aL[kt][2] = pack2bf(l, l2);
        split_bf(w12, h, l); split_bf(w13, h2, l2);
        aH[kt][3] = pack2bf(h, h2); aL[kt][3] = pack2bf(l, l2);
    }

    // h-store base (bf16 units) for (jr0, b0n): kp = jr0>>1
    const int hidx = ((jr0 >> 1) * 8 + b0n) * 2 + (jr0 & 1);

    // init: h0 = 0; stage xp(0), xp(1), xp(2) as separate groups
    for (int i = tid; i < 2 * 64 * 8; i += NTHR) {
        (&uHi[0][0])[i] = 0u;
        (&uLo[0][0])[i] = 0u;
    }
    #pragma unroll
    for (int s = 0; s < 3; s++) {
        if (tid < 128) {
            int b = tid >> 5, seg = tid & 31;
            cp16(&stage[s][b][seg * 4],
                 g_xp + ((long)s * BATCH + bbase + b) * HIDDEN + seg * 4);
        }
        asm volatile("cp.async.commit_group;" ::);
    }
    __syncthreads();

    for (int t = 0; t < SEQ - 1; ++t) {
        const int cur = t & 1, nxt = cur ^ 1;

        // prefetch xp(t+3) -> slot (t+3)&3 (its reader was iter t-1)
        if (t + 3 < SEQ && tid < 128) {
            int b = tid >> 5, seg = tid & 31;
            cp16(&stage[(t + 3) & 3][b][seg * 4],
                 g_xp + ((long)(t + 3) * BATCH + bbase + b) * HIDDEN + seg * 4);
        }
        asm volatile("cp.async.commit_group;" ::);

        // ---- 24 HMMA: three chains of depth 8 ----
        float D1[4] = {0, 0, 0, 0}, D2[4] = {0, 0, 0, 0}, D3[4] = {0, 0, 0, 0};
        #pragma unroll
        for (int kt = 0; kt < NKT; kt++) {
            int wi = (kt * 8 + q) * 8 + g;
            uint32_t bh0 = uHi[cur][wi], bh1 = uHi[cur][wi + 32];
            uint32_t bl0 = uLo[cur][wi], bl1 = uLo[cur][wi + 32];
            mma16816(D1, aH[kt], bh0, bh1);
            mma16816(D2, aL[kt], bh0, bh1);
            mma16816(D3, aH[kt], bl0, bl1);
        }

        asm volatile("cp.async.wait_group 3;" ::);   // xp(t) ready

        // ---- epilogue: + xp, tanh, store h(t+1) ----
        if (act) {
            float xp00 = stage[t & 3][b0n][jr0];
            float xp01 = stage[t & 3][b0n + 1][jr0];
            float xp10 = stage[t & 3][b0n][jr1];
            float xp11 = stage[t & 3][b0n + 1][jr1];
            float h00 = tanh_fast(D1[0] + D2[0] + D3[0] + xp00);
            float h01 = tanh_fast(D1[1] + D2[1] + D3[1] + xp01);
            float h10 = tanh_fast(D1[2] + D2[2] + D3[2] + xp10);
            float h11 = tanh_fast(D1[3] + D2[3] + D3[3] + xp11);
            __nv_bfloat16* phN = reinterpret_cast<__nv_bfloat16*>(&uHi[nxt][0]);
            __nv_bfloat16* plN = reinterpret_cast<__nv_bfloat16*>(&uLo[nxt][0]);
            __nv_bfloat16 hh, ll;
            split_bf(h00, hh, ll); phN[hidx]      = hh; plN[hidx]      = ll;
            split_bf(h01, hh, ll); phN[hidx + 2]  = hh; plN[hidx + 2]  = ll;
            split_bf(h10, hh, ll); phN[hidx + 64] = hh; plN[hidx + 64] = ll;
            split_bf(h11, hh, ll); phN[hidx + 66] = hh; plN[hidx + 66] = ll;
        }
        __syncthreads();
    }

    // ---- peeled final step (t = SEQ-1): h_final -> red ----
    {
        const int t = SEQ - 1, cur = t & 1;
        asm volatile("cp.async.wait_group 0;" ::);
        float D1[4] = {0, 0, 0, 0}, D2[4] = {0, 0, 0, 0}, D3[4] = {0, 0, 0, 0};
        #pragma unroll
        for (int kt = 0; kt < NKT; kt++) {
            int wi = (kt * 8 + q) * 8 + g;
            uint32_t bh0 = uHi[cur][wi], bh1 = uHi[cur][wi + 32];
            uint32_t bl0 = uLo[cur][wi], bl1 = uLo[cur][wi + 32];
            mma16816(D1, aH[kt], bh0, bh1);
            mma16816(D2, aL[kt], bh0, bh1);
            mma16816(D3, aH[kt], bl0, bl1);
        }
        if (act) {
            red[b0n][jr0]     = tanh_fast(D1[0] + D2[0] + D3[0] + stage[t & 3][b0n][jr0]);
            red[b0n + 1][jr0] = tanh_fast(D1[1] + D2[1] + D3[1] + stage[t & 3][b0n + 1][jr0]);
            red[b0n][jr1]     = tanh_fast(D1[2] + D2[2] + D3[2] + stage[t & 3][b0n][jr1]);
            red[b0n + 1][jr1] = tanh_fast(D1[3] + D2[3] + D3[3] + stage[t & 3][b0n + 1][jr1]);
        }
        __syncthreads();
    }

    // ---- output projection ----
    if (wid < BB) {
        int b = wid;
        float s = 0.0f;
        #pragma unroll
        for (int m = 0; m < 4; m++) {
            int jj = lane + 32 * m;
            s += red[b][jj] * W_out[jj];
        }
        #pragma unroll
        for (int off = 16; off; off >>= 1)
            s += __shfl_down_sync(0xffffffffu, s, off);
        if (lane == 0) out[bbase + b] = s + b_out[0];
    }
}

extern "C" void kernel_launch(void* const* d_in, const int* in_sizes, int n_in,
                              void* d_out, int out_size) {
    const float* xs    = (const float*)d_in[0];
    const float* W_ih  = (const float*)d_in[1];
    const float* W_hh  = (const float*)d_in[2];
    const float* b_ih  = (const float*)d_in[3];
    const float* b_hh  = (const float*)d_in[4];
    const float* W_out = (const float*)d_in[5];
    const float* b_out = (const float*)d_in[6];

    xproj_hmma<<<XBLK, 256>>>(xs, W_ih, b_ih, b_hh);
    rnn_hmma_kernel<<<NBLK, NTHR>>>(W_hh, W_out, b_out, (float*)d_out);
}